// round 15
// baseline (speedup 1.0000x reference)
#include <cuda_runtime.h>
#include <cuda_bf16.h>
#include <cstdint>

#define NN 50000
#define NE 800000
#define FIN 128
#define EDIM 64
#define HC 256
#define NH 4
#define CC 64
#define NBCH 49   // number of 1024-node chunks
#define NSPLIT 25600   // agg1/tgemm2 pipeline split (multiple of 8 and 128)

// ---------------- scratch (static device globals; no allocations) ----------
__device__ float g_h[(size_t)NN * HC];
__device__ __nv_bfloat16 g_Ahi[(size_t)NN * HC];
__device__ __nv_bfloat16 g_Alo[(size_t)NN * HC];
__device__ __nv_bfloat16 g_B1hi[FIN * HC];
__device__ __nv_bfloat16 g_B1lo[FIN * HC];
__device__ __nv_bfloat16 g_B2hi[HC * HC];
__device__ __nv_bfloat16 g_B2lo[HC * HC];
__device__ float g_asrc[NN * NH];
__device__ float g_adst[NN * NH];
__device__ float g_le[(size_t)NE * 8];   // per-edge logit terms, CSR ORDER
__device__ float g_M[EDIM * 8];
__device__ int   g_deg[NN];
__device__ int   g_rowptr[NN + 1];
__device__ int   g_fill[NN];
__device__ int   g_csrc[NE];
__device__ int   g_pos[NE];              // edge e -> CSR slot
__device__ int   g_bsum[64];

__device__ __forceinline__ float lrelu(float x) { return x > 0.f ? x : 0.2f * x; }
__device__ __forceinline__ float elu(float x)  { return x > 0.f ? x : (__expf(x) - 1.f); }
__device__ __forceinline__ float pick4(float4 v, int h) {
    return h == 0 ? v.x : (h == 1 ? v.y : (h == 2 ? v.z : v.w));
}

// 32-byte L2-pinned load (sm_103 requires .v8.b32 with evict hints)
struct F8 { float v[8]; };
__device__ __forceinline__ F8 ld_evl8(const float* p) {
    F8 r;
    asm volatile("ld.global.nc.L2::evict_last.v8.b32 {%0,%1,%2,%3,%4,%5,%6,%7}, [%8];"
                 : "=f"(r.v[0]), "=f"(r.v[1]), "=f"(r.v[2]), "=f"(r.v[3]),
                   "=f"(r.v[4]), "=f"(r.v[5]), "=f"(r.v[6]), "=f"(r.v[7])
                 : "l"(p));
    return r;
}
__device__ __forceinline__ void st_cs4(uint4* p, uint4 v) {   // streaming store
    asm volatile("st.global.cs.v4.u32 [%0], {%1,%2,%3,%4};"
                 :: "l"(p), "r"(v.x), "r"(v.y), "r"(v.z), "r"(v.w) : "memory");
}

// ---------------- CSR construction ----------------
// g_deg is zero at entry (zero-init at load; re-zeroed by k_addoff each call).
__global__ void k_deg(const int* __restrict__ dst) {
    int e = blockIdx.x * blockDim.x + threadIdx.x;
    if (e < NE) atomicAdd(&g_deg[dst[e]], 1);
}

__global__ void k_bsum() {
    __shared__ int wsum[32];
    int t = threadIdx.x, lane = t & 31, w = t >> 5;
    int i = blockIdx.x * 1024 + t;
    int v = (i < NN) ? g_deg[i] : 0;
    int x = v;
    #pragma unroll
    for (int o = 1; o < 32; o <<= 1) {
        int y = __shfl_up_sync(0xffffffffu, x, o);
        if (lane >= o) x += y;
    }
    if (lane == 31) wsum[w] = x;
    __syncthreads();
    if (w == 0) {
        int s = wsum[lane];
        #pragma unroll
        for (int o = 1; o < 32; o <<= 1) {
            int y = __shfl_up_sync(0xffffffffu, s, o);
            if (lane >= o) s += y;
        }
        wsum[lane] = s;
    }
    __syncthreads();
    int incl = x + (w ? wsum[w - 1] : 0);
    if (i < NN) g_rowptr[i + 1] = incl;
    if (t == 1023) g_bsum[blockIdx.x] = incl;
}

__global__ void k_addoff() {
    __shared__ int red[2];
    int t = threadIdx.x;
    int chunk = blockIdx.x >> 2;
    if (t < 64) {
        int v = (t < NBCH && t < chunk) ? g_bsum[t] : 0;
        #pragma unroll
        for (int o = 16; o > 0; o >>= 1) v += __shfl_down_sync(0xffffffffu, v, o);
        if ((t & 31) == 0) red[t >> 5] = v;
    }
    __syncthreads();
    int off = red[0] + red[1];
    int i = blockIdx.x * 256 + t;
    if (i < NN) {
        int d = g_deg[i];
        int r = g_rowptr[i + 1] + off;
        g_rowptr[i + 1] = r;
        g_fill[i] = r - d;
        g_deg[i] = 0;
        if (i == 0) g_rowptr[0] = 0;
    }
}

__global__ void k_scatter(const int* __restrict__ src, const int* __restrict__ dst) {
    int e = blockIdx.x * blockDim.x + threadIdx.x;
    if (e < NE) {
        int pos = atomicAdd(&g_fill[dst[e]], 1);
        g_csrc[pos] = src[e];
        g_pos[e] = pos;
    }
}

// ---------------- fold edgeW @ att_edge into M[64][8] (both layers) --------
__global__ void k_M(const float* __restrict__ eW1, const float* __restrict__ ae1,
                    const float* __restrict__ eW2, const float* __restrict__ ae2) {
    int t = threadIdx.x;
    if (t >= 512) return;
    int d = t >> 3, q = t & 7, h = q & 3;
    const float* eW = (q < 4) ? eW1 : eW2;
    const float* ae = (q < 4) ? ae1 : ae2;
    float s = 0.f;
    #pragma unroll 4
    for (int c = 0; c < CC; c++) s += eW[d * HC + h * CC + c] * ae[h * CC + c];
    g_M[d * 8 + q] = s;
}

// ------ per-edge logit terms: le[pos(e)] = edge_feat[e] @ M (CSR order) -----
__global__ void k_elog(const float* __restrict__ ef) {
    __shared__ float sef[32][65];
    __shared__ float sM[512];
    __shared__ int   spos[32];
    int t = threadIdx.x;
    for (int i = t; i < 512; i += 256) sM[i] = g_M[i];
    size_t e0 = (size_t)blockIdx.x * 32;
    if (t < 32) spos[t] = g_pos[e0 + t];
    for (int i = t; i < 512; i += 256) {
        int idx = i * 4;
        int e = idx >> 6, d = idx & 63;
        float4 v = __ldcs((const float4*)(ef + (e0 + e) * EDIM + d));
        sef[e][d] = v.x; sef[e][d + 1] = v.y; sef[e][d + 2] = v.z; sef[e][d + 3] = v.w;
    }
    __syncthreads();
    int e = t >> 3, q = t & 7;
    float s = 0.f;
    #pragma unroll
    for (int d = 0; d < 64; d++) s += sef[e][d] * sM[d * 8 + q];
    g_le[(size_t)spos[e] * 8 + q] = s;
}

// ------- fused MAX-FREE softmax + aggregation + self-loop mean --------------
template <int LAYER>
__global__ __launch_bounds__(256) void k_agg(const float* __restrict__ bias,
                                             float* __restrict__ outp, int noff) {
    __shared__ unsigned long long s_sp[8][128];   // [warp][j*4 + h] = (pe<<32)|src
    int gw = noff + ((blockIdx.x * blockDim.x + threadIdx.x) >> 5);
    if (gw >= NN) return;
    int lane = threadIdx.x & 31;
    int w = (threadIdx.x >> 5) & 7;
    int hq = lane >> 3;
    const int LOFF = (LAYER == 1) ? 0 : 4;

    float4 ans4 = *(const float4*)(g_asrc + gw * 4);
    float4 and4 = *(const float4*)(g_adst + gw * 4);
    float and_x = and4.x, and_y = and4.y, and_z = and4.z, and_w = and4.w;

    float denom = 0.f;
    F8 vn = ld_evl8(g_h + (size_t)gw * HC + lane * 8);
    float acc[8] = {0.f, 0.f, 0.f, 0.f, 0.f, 0.f, 0.f, 0.f};
    float le0 = 0.f, le1 = 0.f, le2 = 0.f, le3 = 0.f;

    int base = g_rowptr[gw], deg = g_rowptr[gw + 1] - base;

    for (int j0 = 0; j0 < deg; j0 += 32) {
        int jj = j0 + lane;
        bool val = jj < deg;
        int s = 0;
        float p0 = 0.f, p1 = 0.f, p2 = 0.f, p3 = 0.f;
        if (val) {
            s = g_csrc[base + jj];
            float4 a4 = *(const float4*)(g_asrc + s * 4);
            float4 l4 = __ldcs((const float4*)(g_le + (size_t)(base + jj) * 8 + LOFF));
            le0 += l4.x; le1 += l4.y; le2 += l4.z; le3 += l4.w;
            p0 = __expf(lrelu(a4.x + and_x + l4.x));
            p1 = __expf(lrelu(a4.y + and_y + l4.y));
            p2 = __expf(lrelu(a4.z + and_z + l4.z));
            p3 = __expf(lrelu(a4.w + and_w + l4.w));
        }
        unsigned long long su = (unsigned)s;
        s_sp[w][lane * 4 + 0] = ((unsigned long long)__float_as_uint(p0) << 32) | su;
        s_sp[w][lane * 4 + 1] = ((unsigned long long)__float_as_uint(p1) << 32) | su;
        s_sp[w][lane * 4 + 2] = ((unsigned long long)__float_as_uint(p2) << 32) | su;
        s_sp[w][lane * 4 + 3] = ((unsigned long long)__float_as_uint(p3) << 32) | su;
        __syncwarp();

        int cnt = min(32, deg - j0);
        int j = 0;
        #pragma unroll 1
        for (; j + 4 <= cnt; j += 4) {
            #pragma unroll
            for (int u = 0; u < 4; u++) {
                unsigned long long v = s_sp[w][(j + u) * 4 + hq];
                int ss_ = (int)(unsigned)v;
                float p = __uint_as_float((unsigned)(v >> 32));
                F8 hw = ld_evl8(g_h + (size_t)ss_ * HC + lane * 8);
                denom += p;
                #pragma unroll
                for (int q = 0; q < 8; q++) acc[q] += p * hw.v[q];
            }
        }
        for (; j < cnt; j++) {
            unsigned long long v = s_sp[w][j * 4 + hq];
            int ss_ = (int)(unsigned)v;
            float p = __uint_as_float((unsigned)(v >> 32));
            F8 hw = ld_evl8(g_h + (size_t)ss_ * HC + lane * 8);
            denom += p;
            #pragma unroll
            for (int q = 0; q < 8; q++) acc[q] += p * hw.v[q];
        }
        __syncwarp();
    }

    // ---- self-loop (mean of incoming le) ----
    #pragma unroll
    for (int o = 16; o > 0; o >>= 1) {
        le0 += __shfl_xor_sync(0xffffffffu, le0, o);
        le1 += __shfl_xor_sync(0xffffffffu, le1, o);
        le2 += __shfl_xor_sync(0xffffffffu, le2, o);
        le3 += __shfl_xor_sync(0xffffffffu, le3, o);
    }
    float invd = 1.f / (float)(deg > 0 ? deg : 1);
    float ls0 = lrelu(ans4.x + and_x + le0 * invd);
    float ls1 = lrelu(ans4.y + and_y + le1 * invd);
    float ls2 = lrelu(ans4.z + and_z + le2 * invd);
    float ls3 = lrelu(ans4.w + and_w + le3 * invd);
    float pself = __expf(pick4(make_float4(ls0, ls1, ls2, ls3), hq));
    denom += pself;
    #pragma unroll
    for (int q = 0; q < 8; q++) acc[q] += pself * vn.v[q];

    float inv = 1.f / (denom + 1e-16f);

    if (LAYER == 1) {
        const float* b = bias + lane * 8;
        float o[8];
        #pragma unroll
        for (int q = 0; q < 8; q++) o[q] = elu(acc[q] * inv + b[q]);
        unsigned short hb[8], lb[8];
        #pragma unroll
        for (int q = 0; q < 8; q++) {
            float v = o[q];
            __nv_bfloat16 h = __float2bfloat16(v);
            hb[q] = __bfloat16_as_ushort(h);
            lb[q] = __bfloat16_as_ushort(__float2bfloat16(v - __bfloat162float(h)));
        }
        uint4 uh, ul;
        uh.x = (unsigned)hb[0] | ((unsigned)hb[1] << 16);
        uh.y = (unsigned)hb[2] | ((unsigned)hb[3] << 16);
        uh.z = (unsigned)hb[4] | ((unsigned)hb[5] << 16);
        uh.w = (unsigned)hb[6] | ((unsigned)hb[7] << 16);
        ul.x = (unsigned)lb[0] | ((unsigned)lb[1] << 16);
        ul.y = (unsigned)lb[2] | ((unsigned)lb[3] << 16);
        ul.z = (unsigned)lb[4] | ((unsigned)lb[5] << 16);
        ul.w = (unsigned)lb[6] | ((unsigned)lb[7] << 16);
        st_cs4((uint4*)(g_Ahi + (size_t)gw * HC + lane * 8), uh);
        st_cs4((uint4*)(g_Alo + (size_t)gw * HC + lane * 8), ul);
    } else {
        float v[8];
        #pragma unroll
        for (int q = 0; q < 8; q++) v[q] = acc[q] * inv;
        #pragma unroll
        for (int q = 0; q < 8; q++) {
            v[q] += __shfl_xor_sync(0xffffffffu, v[q], 8);
            v[q] += __shfl_xor_sync(0xffffffffu, v[q], 16);
        }
        if (lane < 8) {
            float* op = outp + (size_t)gw * 64 + lane * 8;
            const float* b = bias + lane * 8;
            #pragma unroll
            for (int q = 0; q < 8; q++) op[q] = 0.25f * v[q] + b[q];
        }
    }
}

// ---------------- fp32 -> bf16 hi/lo splits (x, W1, W2 in one kernel) ------
__global__ void k_split(const float* __restrict__ x, const float* __restrict__ W1,
                        const float* __restrict__ W2) {
    int i = blockIdx.x * blockDim.x + threadIdx.x;
    const int T0 = NN * FIN, T1 = T0 + FIN * HC, T2 = T1 + HC * HC;
    if (i < T0) {
        float v = x[i];
        __nv_bfloat16 h = __float2bfloat16(v);
        g_Ahi[i] = h;
        g_Alo[i] = __float2bfloat16(v - __bfloat162float(h));
    } else if (i < T1) {
        int j = i - T0;
        float v = W1[j];
        __nv_bfloat16 h = __float2bfloat16(v);
        g_B1hi[j] = h;
        g_B1lo[j] = __float2bfloat16(v - __bfloat162float(h));
    } else if (i < T2) {
        int j = i - T1;
        float v = W2[j];
        __nv_bfloat16 h = __float2bfloat16(v);
        g_B2hi[j] = h;
        g_B2lo[j] = __float2bfloat16(v - __bfloat162float(h));
    }
}

// ---------------- tensor-core GEMM + fused a_src/a_dst epilogue -------------
__device__ __forceinline__ void ldsm_x4(uint32_t addr, uint32_t& r0, uint32_t& r1,
                                        uint32_t& r2, uint32_t& r3) {
    asm volatile("ldmatrix.sync.aligned.m8n8.x4.shared.b16 {%0,%1,%2,%3}, [%4];"
                 : "=r"(r0), "=r"(r1), "=r"(r2), "=r"(r3) : "r"(addr));
}
__device__ __forceinline__ void ldsm_x4t(uint32_t addr, uint32_t& r0, uint32_t& r1,
                                         uint32_t& r2, uint32_t& r3) {
    asm volatile("ldmatrix.sync.aligned.m8n8.x4.trans.shared.b16 {%0,%1,%2,%3}, [%4];"
                 : "=r"(r0), "=r"(r1), "=r"(r2), "=r"(r3) : "r"(addr));
}
__device__ __forceinline__ void mma_bf16(float* c, const uint32_t* a, const uint32_t* b) {
    asm volatile("mma.sync.aligned.m16n8k16.row.col.f32.bf16.bf16.f32 "
                 "{%0,%1,%2,%3}, {%4,%5,%6,%7}, {%8,%9}, {%0,%1,%2,%3};"
                 : "+f"(c[0]), "+f"(c[1]), "+f"(c[2]), "+f"(c[3])
                 : "r"(a[0]), "r"(a[1]), "r"(a[2]), "r"(a[3]), "r"(b[0]), "r"(b[1]));
}
__device__ __forceinline__ void cp16(uint32_t dst, const void* src) {
    asm volatile("cp.async.cg.shared.global [%0], [%1], 16;" :: "r"(dst), "l"(src));
}
__device__ __forceinline__ void cp_commit() {
    asm volatile("cp.async.commit_group;");
}
template <int N>
__device__ __forceinline__ void cp_wait() {
    asm volatile("cp.async.wait_group %0;" :: "n"(N));
}

#define ASTRIDE 24
#define BSTRIDE 72
#define A_ELEMS (128 * ASTRIDE)
#define B_ELEMS (16 * BSTRIDE)

// one block = 128 rows x 64 cols = exactly ONE head (blockIdx.x); rowoff in blocks
__global__ __launch_bounds__(256) void k_tgemm(int layer, int K,
                                               const float* __restrict__ as_,
                                               const float* __restrict__ ad_,
                                               int rowoff) {
    const __nv_bfloat16* __restrict__ Bhi = layer ? g_B2hi : g_B1hi;
    const __nv_bfloat16* __restrict__ Blo = layer ? g_B2lo : g_B1lo;
    const __nv_bfloat16* __restrict__ Ahi = g_Ahi;
    const __nv_bfloat16* __restrict__ Alo = g_Alo;

    __shared__ __align__(16) __nv_bfloat16 sAh[2][A_ELEMS];
    __shared__ __align__(16) __nv_bfloat16 sAl[2][A_ELEMS];
    __shared__ __align__(16) __nv_bfloat16 sBh[2][B_ELEMS];
    __shared__ __align__(16) __nv_bfloat16 sBl[2][B_ELEMS];
    __shared__ float s_red[2][128];

    int tid = threadIdx.x, lane = tid & 31, wid = tid >> 5;
    int row0 = (blockIdx.y + rowoff) * 128, col0 = blockIdx.x * 64;
    int wm0 = (wid >> 1) * 32, wn0 = (wid & 1) * 32;

    float c[2][4][4] = {};

    int arow = tid >> 1, ahalf = tid & 1;
    int grow = row0 + arow;
    size_t agoff = (size_t)(grow < NN ? grow : 0) * K + ahalf * 8;
    int asoff = arow * ASTRIDE + ahalf * 8;
    int bt = tid & 127;
    int brow = bt >> 3, bchunk = bt & 7;
    int bsoff = brow * BSTRIDE + bchunk * 8;
    size_t bgoff = (size_t)brow * HC + col0 + bchunk * 8;

    uint32_t sAh_b = (uint32_t)__cvta_generic_to_shared(sAh);
    uint32_t sAl_b = (uint32_t)__cvta_generic_to_shared(sAl);
    uint32_t sBh_b = (uint32_t)__cvta_generic_to_shared(sBh);
    uint32_t sBl_b = (uint32_t)__cvta_generic_to_shared(sBl);

    uint32_t aoff0 = ((wm0 + (lane & 15)) * ASTRIDE + (lane >> 4) * 8) * 2;
    uint32_t aoff1 = ((wm0 + 16 + (lane & 15)) * ASTRIDE + (lane >> 4) * 8) * 2;
    uint32_t boff0 = ((lane & 15) * BSTRIDE + wn0 + (lane >> 4) * 8) * 2;
    uint32_t boff1 = ((lane & 15) * BSTRIDE + wn0 + 16 + (lane >> 4) * 8) * 2;

    const int nk = K / 16;

    auto load_stage = [&](int kk, int st) {
        uint32_t ab = st * (A_ELEMS * 2);
        cp16(sAh_b + ab + asoff * 2, Ahi + agoff + kk);
        cp16(sAl_b + ab + asoff * 2, Alo + agoff + kk);
        uint32_t bb = st * (B_ELEMS * 2);
        if (tid < 128) cp16(sBh_b + bb + bsoff * 2, Bhi + (size_t)kk * HC + bgoff);
        else           cp16(sBl_b + bb + bsoff * 2, Blo + (size_t)kk * HC + bgoff);
    };

    load_stage(0, 0);
    cp_commit();

    for (int i = 0; i < nk; i++) {
        if (i + 1 < nk) load_stage((i + 1) * 16, (i + 1) & 1);
        cp_commit();
        cp_wait<1>();
        __syncthreads();

        int st = i & 1;
        uint32_t ab = st * (A_ELEMS * 2);
        uint32_t bb = st * (B_ELEMS * 2);
        uint32_t ah[2][4], al[2][4], bh[4][2], bl[4][2];
        ldsm_x4(sAh_b + ab + aoff0, ah[0][0], ah[0][1], ah[0][2], ah[0][3]);
        ldsm_x4(sAh_b + ab + aoff1, ah[1][0], ah[1][1], ah[1][2], ah[1][3]);
        ldsm_x4(sAl_b + ab + aoff0, al[0][0], al[0][1], al[0][2], al[0][3]);
        ldsm_x4(sAl_b + ab + aoff1, al[1][0], al[1][1], al[1][2], al[1][3]);
        ldsm_x4t(sBh_b + bb + boff0, bh[0][0], bh[0][1], bh[1][0], bh[1][1]);
        ldsm_x4t(sBh_b + bb + boff1, bh[2][0], bh[2][1], bh[3][0], bh[3][1]);
        ldsm_x4t(sBl_b + bb + boff0, bl[0][0], bl[0][1], bl[1][0], bl[1][1]);
        ldsm_x4t(sBl_b + bb + boff1, bl[2][0], bl[2][1], bl[3][0], bl[3][1]);

        #pragma unroll
        for (int mi = 0; mi < 2; mi++)
            #pragma unroll
            for (int ni = 0; ni < 4; ni++) {
                mma_bf16(c[mi][ni], ah[mi], bh[ni]);
                mma_bf16(c[mi][ni], ah[mi], bl[ni]);
                mma_bf16(c[mi][ni], al[mi], bh[ni]);
            }
        __syncthreads();
    }

    // ---- write h tile ----
    int rbase = row0 + wm0 + (lane >> 2);
    int cbase = col0 + wn0 + (lane & 3) * 2;
    #pragma unroll
    for (int mi = 0; mi < 2; mi++)
        #pragma unroll
        for (int ni = 0; ni < 4; ni++) {
            int r = rbase + mi * 16;
            int cc = cbase + ni * 8;
            if (r < NN)
                *(float2*)(g_h + (size_t)r * HC + cc) = make_float2(c[mi][ni][0], c[mi][ni][1]);
            if (r + 8 < NN)
                *(float2*)(g_h + (size_t)(r + 8) * HC + cc) = make_float2(c[mi][ni][2], c[mi][ni][3]);
        }

    // ---- fused a_src/a_dst for this head (head = blockIdx.x) ----
    const float* asp = as_ + blockIdx.x * CC;
    const float* adp = ad_ + blockIdx.x * CC;
    float sacc[4] = {0, 0, 0, 0}, dacc[4] = {0, 0, 0, 0};
    #pragma unroll
    for (int ni = 0; ni < 4; ni++) {
        int c0 = wn0 + (lane & 3) * 2 + ni * 8;
        float a0 = asp[c0], a1 = asp[c0 + 1];
        float d0 = adp[c0], d1 = adp[c0 + 1];
        #pragma unroll
        for (int mi = 0; mi < 2; mi++) {
            sacc[mi * 2 + 0] += c[mi][ni][0] * a0 + c[mi][ni][1] * a1;
            sacc[mi * 2 + 1] += c[mi][ni][2] * a0 + c[mi][ni][3] * a1;
            dacc[mi * 2 + 0] += c[mi][ni][0] * d0 + c[mi][ni][1] * d1;
            dacc[mi * 2 + 1] += c[mi][ni][2] * d0 + c[mi][ni][3] * d1;
        }
    }
    #pragma unroll
    for (int q = 0; q < 4; q++) {
        sacc[q] += __shfl_xor_sync(0xffffffffu, sacc[q], 1);
        sacc[q] += __shfl_xor_sync(0xffffffffu, sacc[q], 2);
        dacc[q] += __shfl_xor_sync(0xffffffffu, dacc[q], 1);
        dacc[q] += __shfl_xor_sync(0xffffffffu, dacc[q], 2);
    }
    if ((wid & 1) == 0 && (lane & 3) == 0) {
        #pragma unroll
        for (int q = 0; q < 4; q++) {
            int rr = wm0 + (lane >> 2) + 8 * (q & 1) + 16 * (q >> 1);
            s_red[0][rr] = sacc[q];
            s_red[1][rr] = dacc[q];
        }
    }
    __syncthreads();
    if ((wid & 1) == 1 && (lane & 3) == 0) {
        #pragma unroll
        for (int q = 0; q < 4; q++) {
            int rr = wm0 + (lane >> 2) + 8 * (q & 1) + 16 * (q >> 1);
            int r = row0 + rr;
            if (r < NN) {
                g_asrc[r * 4 + blockIdx.x] = s_red[0][rr] + sacc[q];
                g_adst[r * 4 + blockIdx.x] = s_red[1][rr] + dacc[q];
            }
        }
    }
}

// ---------------- launch ----------------------------------------------------
extern "C" void kernel_launch(void* const* d_in, const int* in_sizes, int n_in,
                              void* d_out, int out_size) {
    const float* x    = (const float*)d_in[0];
    const float* ef   = (const float*)d_in[1];
    const int*   ei   = (const int*)  d_in[2];
    const float* W1   = (const float*)d_in[3];
    const float* as1  = (const float*)d_in[4];
    const float* ad1  = (const float*)d_in[5];
    const float* ae1  = (const float*)d_in[6];
    const float* b1   = (const float*)d_in[7];
    const float* eW1  = (const float*)d_in[8];
    const float* W2   = (const float*)d_in[9];
    const float* as2  = (const float*)d_in[10];
    const float* ad2  = (const float*)d_in[11];
    const float* ae2  = (const float*)d_in[12];
    const float* b2   = (const float*)d_in[13];
    const float* eW2  = (const float*)d_in[14];
    float* out = (float*)d_out;

    const int* src = ei;
    const int* dst = ei + NE;

    const int EB = (NE + 255) / 256;
    const int WB = (NN * 32 + 255) / 256;       // 6250
    const int NB = (NN + 1023) / 1024;          // 49 == NBCH
    const int WB_A = NSPLIT / 8;                // 3200 blocks (nodes 0..25599)
    const int WB_B = (NN - NSPLIT + 7) / 8;     // 3050 blocks
    const int RB_A = NSPLIT / 128;              // 200 row blocks
    const int RB_B = (NN + 127) / 128 - RB_A;   // 191

    static cudaStream_t s2 = nullptr;
    static cudaEvent_t evFork = nullptr, evM = nullptr, evJoin = nullptr;
    static cudaEvent_t evA = nullptr, evB = nullptr, evJ2 = nullptr;
    if (s2 == nullptr) {
        cudaStreamCreateWithFlags(&s2, cudaStreamNonBlocking);
        cudaEventCreateWithFlags(&evFork, cudaEventDisableTiming);
        cudaEventCreateWithFlags(&evM, cudaEventDisableTiming);
        cudaEventCreateWithFlags(&evJoin, cudaEventDisableTiming);
        cudaEventCreateWithFlags(&evA, cudaEventDisableTiming);
        cudaEventCreateWithFlags(&evB, cudaEventDisableTiming);
        cudaEventCreateWithFlags(&evJ2, cudaEventDisableTiming);
    }

    // fork: s2 runs k_M -> k_split -> tgemm(layer1) while main does CSR + elog
    cudaEventRecord(evFork, 0);
    cudaStreamWaitEvent(s2, evFork, 0);

    k_M<<<1, 512, 0, s2>>>(eW1, ae1, eW2, ae2);
    cudaEventRecord(evM, s2);
    k_split<<<(NN * FIN + FIN * HC + HC * HC + 255) / 256, 256, 0, s2>>>(x, W1, W2);
    k_tgemm<<<dim3(4, (NN + 127) / 128), 256, 0, s2>>>(0, FIN, as1, ad1, 0);
    cudaEventRecord(evJoin, s2);

    // main: CSR chain, then edge logits (needs g_M and g_pos)
    k_deg<<<EB, 256>>>(dst);
    k_bsum<<<NB, 1024>>>();
    k_addoff<<<(NN + 255) / 256, 256>>>();
    k_scatter<<<EB, 256>>>(src, dst);
    cudaStreamWaitEvent(0, evM, 0);
    k_elog<<<NE / 32, 256>>>(ef);

    // join: need g_h / g_asrc / g_adst from tgemm1
    cudaStreamWaitEvent(0, evJoin, 0);

    // ---- pipelined agg1 / tgemm2 ----
    k_agg<1><<<WB_A, 256>>>(b1, nullptr, 0);                    // nodes [0, NSPLIT)
    cudaEventRecord(evA, 0);
    cudaStreamWaitEvent(s2, evA, 0);
    k_tgemm<<<dim3(4, RB_A), 256, 0, s2>>>(1, HC, as2, ad2, 0); // rows [0, NSPLIT)

    k_agg<1><<<WB_B, 256>>>(b1, nullptr, NSPLIT);               // nodes [NSPLIT, NN)
    cudaEventRecord(evB, 0);
    cudaStreamWaitEvent(s2, evB, 0);
    k_tgemm<<<dim3(4, RB_B), 256, 0, s2>>>(1, HC, as2, ad2, RB_A);
    cudaEventRecord(evJ2, s2);

    cudaStreamWaitEvent(0, evJ2, 0);
    k_agg<2><<<WB, 256>>>(b2, out, 0);
}

// round 16
// speedup vs baseline: 1.0836x; 1.0836x over previous
#include <cuda_runtime.h>
#include <cuda_bf16.h>
#include <cstdint>

#define NN 50000
#define NE 800000
#define FIN 128
#define EDIM 64
#define HC 256
#define NH 4
#define CC 64
#define NBCH 49   // number of 1024-node chunks

// ---------------- scratch (static device globals; no allocations) ----------
__device__ float g_h[(size_t)NN * HC];
__device__ __nv_bfloat16 g_Ahi[(size_t)NN * HC];
__device__ __nv_bfloat16 g_Alo[(size_t)NN * HC];
__device__ __nv_bfloat16 g_B1hi[FIN * HC];
__device__ __nv_bfloat16 g_B1lo[FIN * HC];
__device__ __nv_bfloat16 g_B2hi[HC * HC];
__device__ __nv_bfloat16 g_B2lo[HC * HC];
__device__ float g_asrc[NN * NH];
__device__ float g_adst[NN * NH];
__device__ float g_le[(size_t)NE * 8];   // per-edge logit terms, CSR ORDER
__device__ float g_M[EDIM * 8];
__device__ int   g_deg[NN];
__device__ int   g_rowptr[NN + 1];
__device__ int   g_fill[NN];
__device__ int   g_csrc[NE];
__device__ int   g_pos[NE];              // edge e -> CSR slot
__device__ int   g_bsum[64];
__device__ int   g_ctr[2];               // work-queue counters (agg layer 1/2)

__device__ __forceinline__ float lrelu(float x) { return x > 0.f ? x : 0.2f * x; }
__device__ __forceinline__ float elu(float x)  { return x > 0.f ? x : (__expf(x) - 1.f); }
__device__ __forceinline__ float pick4(float4 v, int h) {
    return h == 0 ? v.x : (h == 1 ? v.y : (h == 2 ? v.z : v.w));
}

// 32-byte L2-pinned load (sm_103 requires .v8.b32 with evict hints)
struct F8 { float v[8]; };
__device__ __forceinline__ F8 ld_evl8(const float* p) {
    F8 r;
    asm volatile("ld.global.nc.L2::evict_last.v8.b32 {%0,%1,%2,%3,%4,%5,%6,%7}, [%8];"
                 : "=f"(r.v[0]), "=f"(r.v[1]), "=f"(r.v[2]), "=f"(r.v[3]),
                   "=f"(r.v[4]), "=f"(r.v[5]), "=f"(r.v[6]), "=f"(r.v[7])
                 : "l"(p));
    return r;
}
__device__ __forceinline__ void st_cs4(uint4* p, uint4 v) {   // streaming store
    asm volatile("st.global.cs.v4.u32 [%0], {%1,%2,%3,%4};"
                 :: "l"(p), "r"(v.x), "r"(v.y), "r"(v.z), "r"(v.w) : "memory");
}

// ---------------- CSR construction ----------------
// g_deg is zero at entry (zero-init at load; re-zeroed by k_addoff each call).
__global__ void k_deg(const int* __restrict__ dst) {
    int e = blockIdx.x * blockDim.x + threadIdx.x;
    if (e < NE) atomicAdd(&g_deg[dst[e]], 1);
}

__global__ void k_bsum() {
    __shared__ int wsum[32];
    int t = threadIdx.x, lane = t & 31, w = t >> 5;
    int i = blockIdx.x * 1024 + t;
    int v = (i < NN) ? g_deg[i] : 0;
    int x = v;
    #pragma unroll
    for (int o = 1; o < 32; o <<= 1) {
        int y = __shfl_up_sync(0xffffffffu, x, o);
        if (lane >= o) x += y;
    }
    if (lane == 31) wsum[w] = x;
    __syncthreads();
    if (w == 0) {
        int s = wsum[lane];
        #pragma unroll
        for (int o = 1; o < 32; o <<= 1) {
            int y = __shfl_up_sync(0xffffffffu, s, o);
            if (lane >= o) s += y;
        }
        wsum[lane] = s;
    }
    __syncthreads();
    int incl = x + (w ? wsum[w - 1] : 0);
    if (i < NN) g_rowptr[i + 1] = incl;
    if (t == 1023) g_bsum[blockIdx.x] = incl;
}

__global__ void k_addoff() {
    __shared__ int red[2];
    int t = threadIdx.x;
    int chunk = blockIdx.x >> 2;
    if (blockIdx.x == 0 && t < 2) g_ctr[t] = 0;   // reset agg work queues
    if (t < 64) {
        int v = (t < NBCH && t < chunk) ? g_bsum[t] : 0;
        #pragma unroll
        for (int o = 16; o > 0; o >>= 1) v += __shfl_down_sync(0xffffffffu, v, o);
        if ((t & 31) == 0) red[t >> 5] = v;
    }
    __syncthreads();
    int off = red[0] + red[1];
    int i = blockIdx.x * 256 + t;
    if (i < NN) {
        int d = g_deg[i];
        int r = g_rowptr[i + 1] + off;
        g_rowptr[i + 1] = r;
        g_fill[i] = r - d;
        g_deg[i] = 0;
        if (i == 0) g_rowptr[0] = 0;
    }
}

__global__ void k_scatter(const int* __restrict__ src, const int* __restrict__ dst) {
    int e = blockIdx.x * blockDim.x + threadIdx.x;
    if (e < NE) {
        int pos = atomicAdd(&g_fill[dst[e]], 1);
        g_csrc[pos] = src[e];
        g_pos[e] = pos;
    }
}

// ---------------- fold edgeW @ att_edge into M[64][8] (both layers) --------
__global__ void k_M(const float* __restrict__ eW1, const float* __restrict__ ae1,
                    const float* __restrict__ eW2, const float* __restrict__ ae2) {
    int t = threadIdx.x;
    if (t >= 512) return;
    int d = t >> 3, q = t & 7, h = q & 3;
    const float* eW = (q < 4) ? eW1 : eW2;
    const float* ae = (q < 4) ? ae1 : ae2;
    float s = 0.f;
    #pragma unroll 4
    for (int c = 0; c < CC; c++) s += eW[d * HC + h * CC + c] * ae[h * CC + c];
    g_M[d * 8 + q] = s;
}

// ------ per-edge logit terms: le[pos(e)] = edge_feat[e] @ M (CSR order) -----
__global__ void k_elog(const float* __restrict__ ef) {
    __shared__ float sef[32][65];
    __shared__ float sM[512];
    __shared__ int   spos[32];
    int t = threadIdx.x;
    for (int i = t; i < 512; i += 256) sM[i] = g_M[i];
    size_t e0 = (size_t)blockIdx.x * 32;
    if (t < 32) spos[t] = g_pos[e0 + t];
    for (int i = t; i < 512; i += 256) {
        int idx = i * 4;
        int e = idx >> 6, d = idx & 63;
        float4 v = *(const float4*)(ef + (e0 + e) * EDIM + d);
        sef[e][d] = v.x; sef[e][d + 1] = v.y; sef[e][d + 2] = v.z; sef[e][d + 3] = v.w;
    }
    __syncthreads();
    int e = t >> 3, q = t & 7;
    float s = 0.f;
    #pragma unroll
    for (int d = 0; d < 64; d++) s += sef[e][d] * sM[d * 8 + q];
    g_le[(size_t)spos[e] * 8 + q] = s;
}

// ------- fused MAX-FREE softmax + aggregation, PERSISTENT work queue --------
// each warp grabs 4 nodes per atomic; body identical to the fixed-assignment
// version, so per-node output is independent of assignment order.
template <int LAYER>
__global__ __launch_bounds__(256) void k_agg(const float* __restrict__ bias,
                                             float* __restrict__ outp) {
    __shared__ unsigned long long s_sp[8][128];   // [warp][j*4 + h] = (pe<<32)|src
    int lane = threadIdx.x & 31;
    int w = (threadIdx.x >> 5) & 7;
    int hq = lane >> 3;
    const int LOFF = (LAYER == 1) ? 0 : 4;

    for (;;) {
        int n0;
        if (lane == 0) n0 = atomicAdd(&g_ctr[LAYER - 1], 4);
        n0 = __shfl_sync(0xffffffffu, n0, 0);
        if (n0 >= NN) return;
        int nend = min(n0 + 4, NN);

        for (int gw = n0; gw < nend; gw++) {
            float4 ans4 = *(const float4*)(g_asrc + gw * 4);
            float4 and4 = *(const float4*)(g_adst + gw * 4);
            float and_x = and4.x, and_y = and4.y, and_z = and4.z, and_w = and4.w;

            float denom = 0.f;
            F8 vn = ld_evl8(g_h + (size_t)gw * HC + lane * 8);
            float acc[8] = {0.f, 0.f, 0.f, 0.f, 0.f, 0.f, 0.f, 0.f};
            float le0 = 0.f, le1 = 0.f, le2 = 0.f, le3 = 0.f;

            int base = g_rowptr[gw], deg = g_rowptr[gw + 1] - base;

            for (int j0 = 0; j0 < deg; j0 += 32) {
                int jj = j0 + lane;
                bool val = jj < deg;
                int s = 0;
                float p0 = 0.f, p1 = 0.f, p2 = 0.f, p3 = 0.f;
                if (val) {
                    s = g_csrc[base + jj];
                    float4 a4 = *(const float4*)(g_asrc + s * 4);
                    float4 l4 = __ldcs((const float4*)(g_le + (size_t)(base + jj) * 8 + LOFF));
                    le0 += l4.x; le1 += l4.y; le2 += l4.z; le3 += l4.w;
                    p0 = __expf(lrelu(a4.x + and_x + l4.x));
                    p1 = __expf(lrelu(a4.y + and_y + l4.y));
                    p2 = __expf(lrelu(a4.z + and_z + l4.z));
                    p3 = __expf(lrelu(a4.w + and_w + l4.w));
                }
                unsigned long long su = (unsigned)s;
                s_sp[w][lane * 4 + 0] = ((unsigned long long)__float_as_uint(p0) << 32) | su;
                s_sp[w][lane * 4 + 1] = ((unsigned long long)__float_as_uint(p1) << 32) | su;
                s_sp[w][lane * 4 + 2] = ((unsigned long long)__float_as_uint(p2) << 32) | su;
                s_sp[w][lane * 4 + 3] = ((unsigned long long)__float_as_uint(p3) << 32) | su;
                __syncwarp();

                int cnt = min(32, deg - j0);
                int j = 0;
                #pragma unroll 1
                for (; j + 4 <= cnt; j += 4) {
                    #pragma unroll
                    for (int u = 0; u < 4; u++) {
                        unsigned long long v = s_sp[w][(j + u) * 4 + hq];
                        int ss_ = (int)(unsigned)v;
                        float p = __uint_as_float((unsigned)(v >> 32));
                        F8 hw = ld_evl8(g_h + (size_t)ss_ * HC + lane * 8);
                        denom += p;
                        #pragma unroll
                        for (int q = 0; q < 8; q++) acc[q] += p * hw.v[q];
                    }
                }
                for (; j < cnt; j++) {
                    unsigned long long v = s_sp[w][j * 4 + hq];
                    int ss_ = (int)(unsigned)v;
                    float p = __uint_as_float((unsigned)(v >> 32));
                    F8 hw = ld_evl8(g_h + (size_t)ss_ * HC + lane * 8);
                    denom += p;
                    #pragma unroll
                    for (int q = 0; q < 8; q++) acc[q] += p * hw.v[q];
                }
                __syncwarp();
            }

            // ---- self-loop (mean of incoming le) ----
            float t0 = le0, t1 = le1, t2 = le2, t3 = le3;
            #pragma unroll
            for (int o = 16; o > 0; o >>= 1) {
                t0 += __shfl_xor_sync(0xffffffffu, t0, o);
                t1 += __shfl_xor_sync(0xffffffffu, t1, o);
                t2 += __shfl_xor_sync(0xffffffffu, t2, o);
                t3 += __shfl_xor_sync(0xffffffffu, t3, o);
            }
            float invd = 1.f / (float)(deg > 0 ? deg : 1);
            float ls0 = lrelu(ans4.x + and_x + t0 * invd);
            float ls1 = lrelu(ans4.y + and_y + t1 * invd);
            float ls2 = lrelu(ans4.z + and_z + t2 * invd);
            float ls3 = lrelu(ans4.w + and_w + t3 * invd);
            float pself = __expf(pick4(make_float4(ls0, ls1, ls2, ls3), hq));
            denom += pself;
            #pragma unroll
            for (int q = 0; q < 8; q++) acc[q] += pself * vn.v[q];

            float inv = 1.f / (denom + 1e-16f);

            if (LAYER == 1) {
                const float* b = bias + lane * 8;
                float o[8];
                #pragma unroll
                for (int q = 0; q < 8; q++) o[q] = elu(acc[q] * inv + b[q]);
                unsigned short hb[8], lb[8];
                #pragma unroll
                for (int q = 0; q < 8; q++) {
                    float v = o[q];
                    __nv_bfloat16 h = __float2bfloat16(v);
                    hb[q] = __bfloat16_as_ushort(h);
                    lb[q] = __bfloat16_as_ushort(__float2bfloat16(v - __bfloat162float(h)));
                }
                uint4 uh, ul;
                uh.x = (unsigned)hb[0] | ((unsigned)hb[1] << 16);
                uh.y = (unsigned)hb[2] | ((unsigned)hb[3] << 16);
                uh.z = (unsigned)hb[4] | ((unsigned)hb[5] << 16);
                uh.w = (unsigned)hb[6] | ((unsigned)hb[7] << 16);
                ul.x = (unsigned)lb[0] | ((unsigned)lb[1] << 16);
                ul.y = (unsigned)lb[2] | ((unsigned)lb[3] << 16);
                ul.z = (unsigned)lb[4] | ((unsigned)lb[5] << 16);
                ul.w = (unsigned)lb[6] | ((unsigned)lb[7] << 16);
                st_cs4((uint4*)(g_Ahi + (size_t)gw * HC + lane * 8), uh);
                st_cs4((uint4*)(g_Alo + (size_t)gw * HC + lane * 8), ul);
            } else {
                float v[8];
                #pragma unroll
                for (int q = 0; q < 8; q++) v[q] = acc[q] * inv;
                #pragma unroll
                for (int q = 0; q < 8; q++) {
                    v[q] += __shfl_xor_sync(0xffffffffu, v[q], 8);
                    v[q] += __shfl_xor_sync(0xffffffffu, v[q], 16);
                }
                if (lane < 8) {
                    float* op = outp + (size_t)gw * 64 + lane * 8;
                    const float* b = bias + lane * 8;
                    #pragma unroll
                    for (int q = 0; q < 8; q++) op[q] = 0.25f * v[q] + b[q];
                }
            }
        }
    }
}

// ---------------- fp32 -> bf16 hi/lo splits (x, W1, W2 in one kernel) ------
__global__ void k_split(const float* __restrict__ x, const float* __restrict__ W1,
                        const float* __restrict__ W2) {
    int i = blockIdx.x * blockDim.x + threadIdx.x;
    const int T0 = NN * FIN, T1 = T0 + FIN * HC, T2 = T1 + HC * HC;
    if (i < T0) {
        float v = x[i];
        __nv_bfloat16 h = __float2bfloat16(v);
        g_Ahi[i] = h;
        g_Alo[i] = __float2bfloat16(v - __bfloat162float(h));
    } else if (i < T1) {
        int j = i - T0;
        float v = W1[j];
        __nv_bfloat16 h = __float2bfloat16(v);
        g_B1hi[j] = h;
        g_B1lo[j] = __float2bfloat16(v - __bfloat162float(h));
    } else if (i < T2) {
        int j = i - T1;
        float v = W2[j];
        __nv_bfloat16 h = __float2bfloat16(v);
        g_B2hi[j] = h;
        g_B2lo[j] = __float2bfloat16(v - __bfloat162float(h));
    }
}

// ---------------- tensor-core GEMM + fused a_src/a_dst epilogue -------------
__device__ __forceinline__ void ldsm_x4(uint32_t addr, uint32_t& r0, uint32_t& r1,
                                        uint32_t& r2, uint32_t& r3) {
    asm volatile("ldmatrix.sync.aligned.m8n8.x4.shared.b16 {%0,%1,%2,%3}, [%4];"
                 : "=r"(r0), "=r"(r1), "=r"(r2), "=r"(r3) : "r"(addr));
}
__device__ __forceinline__ void ldsm_x4t(uint32_t addr, uint32_t& r0, uint32_t& r1,
                                         uint32_t& r2, uint32_t& r3) {
    asm volatile("ldmatrix.sync.aligned.m8n8.x4.trans.shared.b16 {%0,%1,%2,%3}, [%4];"
                 : "=r"(r0), "=r"(r1), "=r"(r2), "=r"(r3) : "r"(addr));
}
__device__ __forceinline__ void mma_bf16(float* c, const uint32_t* a, const uint32_t* b) {
    asm volatile("mma.sync.aligned.m16n8k16.row.col.f32.bf16.bf16.f32 "
                 "{%0,%1,%2,%3}, {%4,%5,%6,%7}, {%8,%9}, {%0,%1,%2,%3};"
                 : "+f"(c[0]), "+f"(c[1]), "+f"(c[2]), "+f"(c[3])
                 : "r"(a[0]), "r"(a[1]), "r"(a[2]), "r"(a[3]), "r"(b[0]), "r"(b[1]));
}
__device__ __forceinline__ void cp16(uint32_t dst, const void* src) {
    asm volatile("cp.async.cg.shared.global [%0], [%1], 16;" :: "r"(dst), "l"(src));
}
__device__ __forceinline__ void cp_commit() {
    asm volatile("cp.async.commit_group;");
}
template <int N>
__device__ __forceinline__ void cp_wait() {
    asm volatile("cp.async.wait_group %0;" :: "n"(N));
}

#define ASTRIDE 24
#define BSTRIDE 72
#define A_ELEMS (128 * ASTRIDE)
#define B_ELEMS (16 * BSTRIDE)

// one block = 128 rows x 64 cols = exactly ONE head (blockIdx.x)
__global__ __launch_bounds__(256) void k_tgemm(int layer, int K,
                                               const float* __restrict__ as_,
                                               const float* __restrict__ ad_) {
    const __nv_bfloat16* __restrict__ Bhi = layer ? g_B2hi : g_B1hi;
    const __nv_bfloat16* __restrict__ Blo = layer ? g_B2lo : g_B1lo;
    const __nv_bfloat16* __restrict__ Ahi = g_Ahi;
    const __nv_bfloat16* __restrict__ Alo = g_Alo;

    __shared__ __align__(16) __nv_bfloat16 sAh[2][A_ELEMS];
    __shared__ __align__(16) __nv_bfloat16 sAl[2][A_ELEMS];
    __shared__ __align__(16) __nv_bfloat16 sBh[2][B_ELEMS];
    __shared__ __align__(16) __nv_bfloat16 sBl[2][B_ELEMS];
    __shared__ float s_red[2][128];

    int tid = threadIdx.x, lane = tid & 31, wid = tid >> 5;
    int row0 = blockIdx.y * 128, col0 = blockIdx.x * 64;
    int wm0 = (wid >> 1) * 32, wn0 = (wid & 1) * 32;

    float c[2][4][4] = {};

    int arow = tid >> 1, ahalf = tid & 1;
    int grow = row0 + arow;
    size_t agoff = (size_t)(grow < NN ? grow : 0) * K + ahalf * 8;
    int asoff = arow * ASTRIDE + ahalf * 8;
    int bt = tid & 127;
    int brow = bt >> 3, bchunk = bt & 7;
    int bsoff = brow * BSTRIDE + bchunk * 8;
    size_t bgoff = (size_t)brow * HC + col0 + bchunk * 8;

    uint32_t sAh_b = (uint32_t)__cvta_generic_to_shared(sAh);
    uint32_t sAl_b = (uint32_t)__cvta_generic_to_shared(sAl);
    uint32_t sBh_b = (uint32_t)__cvta_generic_to_shared(sBh);
    uint32_t sBl_b = (uint32_t)__cvta_generic_to_shared(sBl);

    uint32_t aoff0 = ((wm0 + (lane & 15)) * ASTRIDE + (lane >> 4) * 8) * 2;
    uint32_t aoff1 = ((wm0 + 16 + (lane & 15)) * ASTRIDE + (lane >> 4) * 8) * 2;
    uint32_t boff0 = ((lane & 15) * BSTRIDE + wn0 + (lane >> 4) * 8) * 2;
    uint32_t boff1 = ((lane & 15) * BSTRIDE + wn0 + 16 + (lane >> 4) * 8) * 2;

    const int nk = K / 16;

    auto load_stage = [&](int kk, int st) {
        uint32_t ab = st * (A_ELEMS * 2);
        cp16(sAh_b + ab + asoff * 2, Ahi + agoff + kk);
        cp16(sAl_b + ab + asoff * 2, Alo + agoff + kk);
        uint32_t bb = st * (B_ELEMS * 2);
        if (tid < 128) cp16(sBh_b + bb + bsoff * 2, Bhi + (size_t)kk * HC + bgoff);
        else           cp16(sBl_b + bb + bsoff * 2, Blo + (size_t)kk * HC + bgoff);
    };

    load_stage(0, 0);
    cp_commit();

    for (int i = 0; i < nk; i++) {
        if (i + 1 < nk) load_stage((i + 1) * 16, (i + 1) & 1);
        cp_commit();
        cp_wait<1>();
        __syncthreads();

        int st = i & 1;
        uint32_t ab = st * (A_ELEMS * 2);
        uint32_t bb = st * (B_ELEMS * 2);
        uint32_t ah[2][4], al[2][4], bh[4][2], bl[4][2];
        ldsm_x4(sAh_b + ab + aoff0, ah[0][0], ah[0][1], ah[0][2], ah[0][3]);
        ldsm_x4(sAh_b + ab + aoff1, ah[1][0], ah[1][1], ah[1][2], ah[1][3]);
        ldsm_x4(sAl_b + ab + aoff0, al[0][0], al[0][1], al[0][2], al[0][3]);
        ldsm_x4(sAl_b + ab + aoff1, al[1][0], al[1][1], al[1][2], al[1][3]);
        ldsm_x4t(sBh_b + bb + boff0, bh[0][0], bh[0][1], bh[1][0], bh[1][1]);
        ldsm_x4t(sBh_b + bb + boff1, bh[2][0], bh[2][1], bh[3][0], bh[3][1]);
        ldsm_x4t(sBl_b + bb + boff0, bl[0][0], bl[0][1], bl[1][0], bl[1][1]);
        ldsm_x4t(sBl_b + bb + boff1, bl[2][0], bl[2][1], bl[3][0], bl[3][1]);

        #pragma unroll
        for (int mi = 0; mi < 2; mi++)
            #pragma unroll
            for (int ni = 0; ni < 4; ni++) {
                mma_bf16(c[mi][ni], ah[mi], bh[ni]);
                mma_bf16(c[mi][ni], ah[mi], bl[ni]);
                mma_bf16(c[mi][ni], al[mi], bh[ni]);
            }
        __syncthreads();
    }

    // ---- write h tile ----
    int rbase = row0 + wm0 + (lane >> 2);
    int cbase = col0 + wn0 + (lane & 3) * 2;
    #pragma unroll
    for (int mi = 0; mi < 2; mi++)
        #pragma unroll
        for (int ni = 0; ni < 4; ni++) {
            int r = rbase + mi * 16;
            int cc = cbase + ni * 8;
            if (r < NN)
                *(float2*)(g_h + (size_t)r * HC + cc) = make_float2(c[mi][ni][0], c[mi][ni][1]);
            if (r + 8 < NN)
                *(float2*)(g_h + (size_t)(r + 8) * HC + cc) = make_float2(c[mi][ni][2], c[mi][ni][3]);
        }

    // ---- fused a_src/a_dst for this head (head = blockIdx.x) ----
    const float* asp = as_ + blockIdx.x * CC;
    const float* adp = ad_ + blockIdx.x * CC;
    float sacc[4] = {0, 0, 0, 0}, dacc[4] = {0, 0, 0, 0};
    #pragma unroll
    for (int ni = 0; ni < 4; ni++) {
        int c0 = wn0 + (lane & 3) * 2 + ni * 8;
        float a0 = asp[c0], a1 = asp[c0 + 1];
        float d0 = adp[c0], d1 = adp[c0 + 1];
        #pragma unroll
        for (int mi = 0; mi < 2; mi++) {
            sacc[mi * 2 + 0] += c[mi][ni][0] * a0 + c[mi][ni][1] * a1;
            sacc[mi * 2 + 1] += c[mi][ni][2] * a0 + c[mi][ni][3] * a1;
            dacc[mi * 2 + 0] += c[mi][ni][0] * d0 + c[mi][ni][1] * d1;
            dacc[mi * 2 + 1] += c[mi][ni][2] * d0 + c[mi][ni][3] * d1;
        }
    }
    #pragma unroll
    for (int q = 0; q < 4; q++) {
        sacc[q] += __shfl_xor_sync(0xffffffffu, sacc[q], 1);
        sacc[q] += __shfl_xor_sync(0xffffffffu, sacc[q], 2);
        dacc[q] += __shfl_xor_sync(0xffffffffu, dacc[q], 1);
        dacc[q] += __shfl_xor_sync(0xffffffffu, dacc[q], 2);
    }
    if ((wid & 1) == 0 && (lane & 3) == 0) {
        #pragma unroll
        for (int q = 0; q < 4; q++) {
            int rr = wm0 + (lane >> 2) + 8 * (q & 1) + 16 * (q >> 1);
            s_red[0][rr] = sacc[q];
            s_red[1][rr] = dacc[q];
        }
    }
    __syncthreads();
    if ((wid & 1) == 1 && (lane & 3) == 0) {
        #pragma unroll
        for (int q = 0; q < 4; q++) {
            int rr = wm0 + (lane >> 2) + 8 * (q & 1) + 16 * (q >> 1);
            int r = row0 + rr;
            if (r < NN) {
                g_asrc[r * 4 + blockIdx.x] = s_red[0][rr] + sacc[q];
                g_adst[r * 4 + blockIdx.x] = s_red[1][rr] + dacc[q];
            }
        }
    }
}

// ---------------- launch ----------------------------------------------------
extern "C" void kernel_launch(void* const* d_in, const int* in_sizes, int n_in,
                              void* d_out, int out_size) {
    const float* x    = (const float*)d_in[0];
    const float* ef   = (const float*)d_in[1];
    const int*   ei   = (const int*)  d_in[2];
    const float* W1   = (const float*)d_in[3];
    const float* as1  = (const float*)d_in[4];
    const float* ad1  = (const float*)d_in[5];
    const float* ae1  = (const float*)d_in[6];
    const float* b1   = (const float*)d_in[7];
    const float* eW1  = (const float*)d_in[8];
    const float* W2   = (const float*)d_in[9];
    const float* as2  = (const float*)d_in[10];
    const float* ad2  = (const float*)d_in[11];
    const float* ae2  = (const float*)d_in[12];
    const float* b2   = (const float*)d_in[13];
    const float* eW2  = (const float*)d_in[14];
    float* out = (float*)d_out;

    const int* src = ei;
    const int* dst = ei + NE;

    const int EB = (NE + 255) / 256;
    const int NB = (NN + 1023) / 1024;      // 49 == NBCH
    const int PB = 1184;                    // persistent agg blocks (~8/SM x 148)
    const dim3 GG(4, (NN + 127) / 128);

    static cudaStream_t s2 = nullptr;
    static cudaEvent_t evFork = nullptr, evM = nullptr, evJoin = nullptr;
    if (s2 == nullptr) {
        cudaStreamCreateWithFlags(&s2, cudaStreamNonBlocking);
        cudaEventCreateWithFlags(&evFork, cudaEventDisableTiming);
        cudaEventCreateWithFlags(&evM, cudaEventDisableTiming);
        cudaEventCreateWithFlags(&evJoin, cudaEventDisableTiming);
    }

    // fork: s2 runs k_M -> k_split -> tgemm(layer1) while main does CSR + elog
    cudaEventRecord(evFork, 0);
    cudaStreamWaitEvent(s2, evFork, 0);

    k_M<<<1, 512, 0, s2>>>(eW1, ae1, eW2, ae2);
    cudaEventRecord(evM, s2);
    k_split<<<(NN * FIN + FIN * HC + HC * HC + 255) / 256, 256, 0, s2>>>(x, W1, W2);
    k_tgemm<<<GG, 256, 0, s2>>>(0, FIN, as1, ad1);
    cudaEventRecord(evJoin, s2);

    // main: CSR chain, then edge logits (needs g_M and g_pos)
    k_deg<<<EB, 256>>>(dst);
    k_bsum<<<NB, 1024>>>();
    k_addoff<<<(NN + 255) / 256, 256>>>();
    k_scatter<<<EB, 256>>>(src, dst);
    cudaStreamWaitEvent(0, evM, 0);
    k_elog<<<NE / 32, 256>>>(ef);

    // join: need g_h / g_asrc / g_adst from tgemm1
    cudaStreamWaitEvent(0, evJoin, 0);

    // layer 1 aggregation (persistent work queue)
    k_agg<1><<<PB, 256>>>(b1, nullptr);

    // layer 2
    k_tgemm<<<GG, 256>>>(1, HC, as2, ad2);
    k_agg<2><<<PB, 256>>>(b2, out);
}

// round 17
// speedup vs baseline: 1.1075x; 1.0221x over previous
#include <cuda_runtime.h>
#include <cuda_bf16.h>
#include <cstdint>

#define NN 50000
#define NE 800000
#define FIN 128
#define EDIM 64
#define HC 256
#define NH 4
#define CC 64
#define NBCH 49   // number of 1024-node chunks

// ---------------- scratch (static device globals; no allocations) ----------
__device__ float g_h[(size_t)NN * HC];
__device__ __nv_bfloat16 g_Ahi[(size_t)NN * HC];
__device__ __nv_bfloat16 g_Alo[(size_t)NN * HC];
__device__ __nv_bfloat16 g_B1hi[FIN * HC];
__device__ __nv_bfloat16 g_B1lo[FIN * HC];
__device__ __nv_bfloat16 g_B2hi[HC * HC];
__device__ __nv_bfloat16 g_B2lo[HC * HC];
__device__ float g_asrc[NN * NH];
__device__ float g_adst[NN * NH];
__device__ float g_le1[(size_t)NE * 4];  // per-edge logit terms layer1, CSR order
__device__ float g_le2[(size_t)NE * 4];  // per-edge logit terms layer2, CSR order
__device__ float g_M[EDIM * 8];
__device__ int   g_deg[NN];
__device__ int   g_rowptr[NN + 1];
__device__ int   g_fill[NN];
__device__ int   g_csrc[NE];
__device__ int   g_pos[NE];              // edge e -> CSR slot
__device__ int   g_bsum[64];
__device__ int   g_ctr[2];               // work-queue counters (agg layer 1/2)

__device__ __forceinline__ float lrelu(float x) { return x > 0.f ? x : 0.2f * x; }
__device__ __forceinline__ float elu(float x)  { return x > 0.f ? x : (__expf(x) - 1.f); }
__device__ __forceinline__ float pick4(float4 v, int h) {
    return h == 0 ? v.x : (h == 1 ? v.y : (h == 2 ? v.z : v.w));
}

// 32-byte L2-pinned load (sm_103 requires .v8.b32 with evict hints)
struct F8 { float v[8]; };
__device__ __forceinline__ F8 ld_evl8(const float* p) {
    F8 r;
    asm volatile("ld.global.nc.L2::evict_last.v8.b32 {%0,%1,%2,%3,%4,%5,%6,%7}, [%8];"
                 : "=f"(r.v[0]), "=f"(r.v[1]), "=f"(r.v[2]), "=f"(r.v[3]),
                   "=f"(r.v[4]), "=f"(r.v[5]), "=f"(r.v[6]), "=f"(r.v[7])
                 : "l"(p));
    return r;
}
__device__ __forceinline__ void st_cs4(uint4* p, uint4 v) {   // streaming store
    asm volatile("st.global.cs.v4.u32 [%0], {%1,%2,%3,%4};"
                 :: "l"(p), "r"(v.x), "r"(v.y), "r"(v.z), "r"(v.w) : "memory");
}

// ---------------- CSR construction ----------------
// g_deg is zero at entry (zero-init at load; re-zeroed by k_addoff each call).
__global__ void k_deg(const int* __restrict__ dst) {
    int e = blockIdx.x * blockDim.x + threadIdx.x;
    if (e < NE) atomicAdd(&g_deg[dst[e]], 1);
}

__global__ void k_bsum() {
    __shared__ int wsum[32];
    int t = threadIdx.x, lane = t & 31, w = t >> 5;
    int i = blockIdx.x * 1024 + t;
    int v = (i < NN) ? g_deg[i] : 0;
    int x = v;
    #pragma unroll
    for (int o = 1; o < 32; o <<= 1) {
        int y = __shfl_up_sync(0xffffffffu, x, o);
        if (lane >= o) x += y;
    }
    if (lane == 31) wsum[w] = x;
    __syncthreads();
    if (w == 0) {
        int s = wsum[lane];
        #pragma unroll
        for (int o = 1; o < 32; o <<= 1) {
            int y = __shfl_up_sync(0xffffffffu, s, o);
            if (lane >= o) s += y;
        }
        wsum[lane] = s;
    }
    __syncthreads();
    int incl = x + (w ? wsum[w - 1] : 0);
    if (i < NN) g_rowptr[i + 1] = incl;
    if (t == 1023) g_bsum[blockIdx.x] = incl;
}

__global__ void k_addoff() {
    __shared__ int red[2];
    int t = threadIdx.x;
    int chunk = blockIdx.x >> 2;
    if (blockIdx.x == 0 && t < 2) g_ctr[t] = 0;   // reset agg work queues
    if (t < 64) {
        int v = (t < NBCH && t < chunk) ? g_bsum[t] : 0;
        #pragma unroll
        for (int o = 16; o > 0; o >>= 1) v += __shfl_down_sync(0xffffffffu, v, o);
        if ((t & 31) == 0) red[t >> 5] = v;
    }
    __syncthreads();
    int off = red[0] + red[1];
    int i = blockIdx.x * 256 + t;
    if (i < NN) {
        int d = g_deg[i];
        int r = g_rowptr[i + 1] + off;
        g_rowptr[i + 1] = r;
        g_fill[i] = r - d;
        g_deg[i] = 0;
        if (i == 0) g_rowptr[0] = 0;
    }
}

__global__ void k_scatter(const int* __restrict__ src, const int* __restrict__ dst) {
    int e = blockIdx.x * blockDim.x + threadIdx.x;
    if (e < NE) {
        int pos = atomicAdd(&g_fill[dst[e]], 1);
        g_csrc[pos] = src[e];
        g_pos[e] = pos;
    }
}

// ---------------- fold edgeW @ att_edge into M[64][8] (both layers) --------
__global__ void k_M(const float* __restrict__ eW1, const float* __restrict__ ae1,
                    const float* __restrict__ eW2, const float* __restrict__ ae2) {
    int t = threadIdx.x;
    if (t >= 512) return;
    int d = t >> 3, q = t & 7, h = q & 3;
    const float* eW = (q < 4) ? eW1 : eW2;
    const float* ae = (q < 4) ? ae1 : ae2;
    float s = 0.f;
    #pragma unroll 4
    for (int c = 0; c < CC; c++) s += eW[d * HC + h * CC + c] * ae[h * CC + c];
    g_M[d * 8 + q] = s;
}

// ------ per-edge logit terms (CSR order, split per layer for dense reads) ---
__global__ void k_elog(const float* __restrict__ ef) {
    __shared__ float sef[32][65];
    __shared__ float sM[512];
    __shared__ int   spos[32];
    int t = threadIdx.x;
    for (int i = t; i < 512; i += 256) sM[i] = g_M[i];
    size_t e0 = (size_t)blockIdx.x * 32;
    if (t < 32) spos[t] = g_pos[e0 + t];
    for (int i = t; i < 512; i += 256) {
        int idx = i * 4;
        int e = idx >> 6, d = idx & 63;
        float4 v = *(const float4*)(ef + (e0 + e) * EDIM + d);
        sef[e][d] = v.x; sef[e][d + 1] = v.y; sef[e][d + 2] = v.z; sef[e][d + 3] = v.w;
    }
    __syncthreads();
    int e = t >> 3, q = t & 7;
    float s = 0.f;
    #pragma unroll
    for (int d = 0; d < 64; d++) s += sef[e][d] * sM[d * 8 + q];
    if (q < 4) g_le1[(size_t)spos[e] * 4 + q] = s;
    else       g_le2[(size_t)spos[e] * 4 + (q - 4)] = s;
}

// ------- fused MAX-FREE softmax + aggregation, PERSISTENT work queue --------
template <int LAYER>
__global__ __launch_bounds__(256) void k_agg(const float* __restrict__ bias,
                                             float* __restrict__ outp) {
    __shared__ unsigned long long s_sp[8][128];   // [warp][j*4 + h] = (pe<<32)|src
    int lane = threadIdx.x & 31;
    int w = (threadIdx.x >> 5) & 7;
    int hq = lane >> 3;
    const float* __restrict__ LEP = (LAYER == 1) ? g_le1 : g_le2;

    for (;;) {
        int n0;
        if (lane == 0) n0 = atomicAdd(&g_ctr[LAYER - 1], 4);
        n0 = __shfl_sync(0xffffffffu, n0, 0);
        if (n0 >= NN) return;
        int nend = min(n0 + 4, NN);

        for (int gw = n0; gw < nend; gw++) {
            float4 ans4 = *(const float4*)(g_asrc + gw * 4);
            float4 and4 = *(const float4*)(g_adst + gw * 4);
            float and_x = and4.x, and_y = and4.y, and_z = and4.z, and_w = and4.w;

            float denom = 0.f;
            F8 vn = ld_evl8(g_h + (size_t)gw * HC + lane * 8);
            float acc[8] = {0.f, 0.f, 0.f, 0.f, 0.f, 0.f, 0.f, 0.f};
            float le0 = 0.f, le1 = 0.f, le2 = 0.f, le3 = 0.f;

            int base = g_rowptr[gw], deg = g_rowptr[gw + 1] - base;

            for (int j0 = 0; j0 < deg; j0 += 32) {
                int jj = j0 + lane;
                bool val = jj < deg;
                int s = 0;
                float p0 = 0.f, p1 = 0.f, p2 = 0.f, p3 = 0.f;
                if (val) {
                    s = __ldcs(g_csrc + base + jj);
                    float4 a4 = *(const float4*)(g_asrc + s * 4);
                    float4 l4 = __ldcs((const float4*)(LEP + (size_t)(base + jj) * 4));
                    le0 += l4.x; le1 += l4.y; le2 += l4.z; le3 += l4.w;
                    p0 = __expf(lrelu(a4.x + and_x + l4.x));
                    p1 = __expf(lrelu(a4.y + and_y + l4.y));
                    p2 = __expf(lrelu(a4.z + and_z + l4.z));
                    p3 = __expf(lrelu(a4.w + and_w + l4.w));
                }
                unsigned long long su = (unsigned)s;
                s_sp[w][lane * 4 + 0] = ((unsigned long long)__float_as_uint(p0) << 32) | su;
                s_sp[w][lane * 4 + 1] = ((unsigned long long)__float_as_uint(p1) << 32) | su;
                s_sp[w][lane * 4 + 2] = ((unsigned long long)__float_as_uint(p2) << 32) | su;
                s_sp[w][lane * 4 + 3] = ((unsigned long long)__float_as_uint(p3) << 32) | su;
                __syncwarp();

                int cnt = min(32, deg - j0);
                int j = 0;
                #pragma unroll 1
                for (; j + 8 <= cnt; j += 8) {
                    #pragma unroll
                    for (int u = 0; u < 8; u++) {
                        unsigned long long v = s_sp[w][(j + u) * 4 + hq];
                        int ss_ = (int)(unsigned)v;
                        float p = __uint_as_float((unsigned)(v >> 32));
                        F8 hw = ld_evl8(g_h + (size_t)ss_ * HC + lane * 8);
                        denom += p;
                        #pragma unroll
                        for (int q = 0; q < 8; q++) acc[q] += p * hw.v[q];
                    }
                }
                for (; j < cnt; j++) {
                    unsigned long long v = s_sp[w][j * 4 + hq];
                    int ss_ = (int)(unsigned)v;
                    float p = __uint_as_float((unsigned)(v >> 32));
                    F8 hw = ld_evl8(g_h + (size_t)ss_ * HC + lane * 8);
                    denom += p;
                    #pragma unroll
                    for (int q = 0; q < 8; q++) acc[q] += p * hw.v[q];
                }
                __syncwarp();
            }

            // ---- self-loop (mean of incoming le) ----
            float t0 = le0, t1 = le1, t2 = le2, t3 = le3;
            #pragma unroll
            for (int o = 16; o > 0; o >>= 1) {
                t0 += __shfl_xor_sync(0xffffffffu, t0, o);
                t1 += __shfl_xor_sync(0xffffffffu, t1, o);
                t2 += __shfl_xor_sync(0xffffffffu, t2, o);
                t3 += __shfl_xor_sync(0xffffffffu, t3, o);
            }
            float invd = 1.f / (float)(deg > 0 ? deg : 1);
            float ls0 = lrelu(ans4.x + and_x + t0 * invd);
            float ls1 = lrelu(ans4.y + and_y + t1 * invd);
            float ls2 = lrelu(ans4.z + and_z + t2 * invd);
            float ls3 = lrelu(ans4.w + and_w + t3 * invd);
            float pself = __expf(pick4(make_float4(ls0, ls1, ls2, ls3), hq));
            denom += pself;
            #pragma unroll
            for (int q = 0; q < 8; q++) acc[q] += pself * vn.v[q];

            float inv = 1.f / (denom + 1e-16f);

            if (LAYER == 1) {
                const float* b = bias + lane * 8;
                float o[8];
                #pragma unroll
                for (int q = 0; q < 8; q++) o[q] = elu(acc[q] * inv + b[q]);
                unsigned short hb[8], lb[8];
                #pragma unroll
                for (int q = 0; q < 8; q++) {
                    float v = o[q];
                    __nv_bfloat16 h = __float2bfloat16(v);
                    hb[q] = __bfloat16_as_ushort(h);
                    lb[q] = __bfloat16_as_ushort(__float2bfloat16(v - __bfloat162float(h)));
                }
                uint4 uh, ul;
                uh.x = (unsigned)hb[0] | ((unsigned)hb[1] << 16);
                uh.y = (unsigned)hb[2] | ((unsigned)hb[3] << 16);
                uh.z = (unsigned)hb[4] | ((unsigned)hb[5] << 16);
                uh.w = (unsigned)hb[6] | ((unsigned)hb[7] << 16);
                ul.x = (unsigned)lb[0] | ((unsigned)lb[1] << 16);
                ul.y = (unsigned)lb[2] | ((unsigned)lb[3] << 16);
                ul.z = (unsigned)lb[4] | ((unsigned)lb[5] << 16);
                ul.w = (unsigned)lb[6] | ((unsigned)lb[7] << 16);
                st_cs4((uint4*)(g_Ahi + (size_t)gw * HC + lane * 8), uh);
                st_cs4((uint4*)(g_Alo + (size_t)gw * HC + lane * 8), ul);
            } else {
                float v[8];
                #pragma unroll
                for (int q = 0; q < 8; q++) v[q] = acc[q] * inv;
                #pragma unroll
                for (int q = 0; q < 8; q++) {
                    v[q] += __shfl_xor_sync(0xffffffffu, v[q], 8);
                    v[q] += __shfl_xor_sync(0xffffffffu, v[q], 16);
                }
                if (lane < 8) {
                    float* op = outp + (size_t)gw * 64 + lane * 8;
                    const float* b = bias + lane * 8;
                    #pragma unroll
                    for (int q = 0; q < 8; q++) op[q] = 0.25f * v[q] + b[q];
                }
            }
        }
    }
}

// ---------------- fp32 -> bf16 hi/lo splits (x, W1, W2 in one kernel) ------
__global__ void k_split(const float* __restrict__ x, const float* __restrict__ W1,
                        const float* __restrict__ W2) {
    int i = blockIdx.x * blockDim.x + threadIdx.x;
    const int T0 = NN * FIN, T1 = T0 + FIN * HC, T2 = T1 + HC * HC;
    if (i < T0) {
        float v = x[i];
        __nv_bfloat16 h = __float2bfloat16(v);
        g_Ahi[i] = h;
        g_Alo[i] = __float2bfloat16(v - __bfloat162float(h));
    } else if (i < T1) {
        int j = i - T0;
        float v = W1[j];
        __nv_bfloat16 h = __float2bfloat16(v);
        g_B1hi[j] = h;
        g_B1lo[j] = __float2bfloat16(v - __bfloat162float(h));
    } else if (i < T2) {
        int j = i - T1;
        float v = W2[j];
        __nv_bfloat16 h = __float2bfloat16(v);
        g_B2hi[j] = h;
        g_B2lo[j] = __float2bfloat16(v - __bfloat162float(h));
    }
}

// ---------------- tensor-core GEMM + fused a_src/a_dst epilogue -------------
__device__ __forceinline__ void ldsm_x4(uint32_t addr, uint32_t& r0, uint32_t& r1,
                                        uint32_t& r2, uint32_t& r3) {
    asm volatile("ldmatrix.sync.aligned.m8n8.x4.shared.b16 {%0,%1,%2,%3}, [%4];"
                 : "=r"(r0), "=r"(r1), "=r"(r2), "=r"(r3) : "r"(addr));
}
__device__ __forceinline__ void ldsm_x4t(uint32_t addr, uint32_t& r0, uint32_t& r1,
                                         uint32_t& r2, uint32_t& r3) {
    asm volatile("ldmatrix.sync.aligned.m8n8.x4.trans.shared.b16 {%0,%1,%2,%3}, [%4];"
                 : "=r"(r0), "=r"(r1), "=r"(r2), "=r"(r3) : "r"(addr));
}
__device__ __forceinline__ void mma_bf16(float* c, const uint32_t* a, const uint32_t* b) {
    asm volatile("mma.sync.aligned.m16n8k16.row.col.f32.bf16.bf16.f32 "
                 "{%0,%1,%2,%3}, {%4,%5,%6,%7}, {%8,%9}, {%0,%1,%2,%3};"
                 : "+f"(c[0]), "+f"(c[1]), "+f"(c[2]), "+f"(c[3])
                 : "r"(a[0]), "r"(a[1]), "r"(a[2]), "r"(a[3]), "r"(b[0]), "r"(b[1]));
}
__device__ __forceinline__ void cp16(uint32_t dst, const void* src) {
    asm volatile("cp.async.cg.shared.global [%0], [%1], 16;" :: "r"(dst), "l"(src));
}
__device__ __forceinline__ void cp_commit() {
    asm volatile("cp.async.commit_group;");
}
template <int N>
__device__ __forceinline__ void cp_wait() {
    asm volatile("cp.async.wait_group %0;" :: "n"(N));
}

#define ASTRIDE 24
#define BSTRIDE 72
#define A_ELEMS (128 * ASTRIDE)
#define B_ELEMS (16 * BSTRIDE)

// one block = 128 rows x 64 cols = exactly ONE head (blockIdx.x)
__global__ __launch_bounds__(256) void k_tgemm(int layer, int K,
                                               const float* __restrict__ as_,
                                               const float* __restrict__ ad_) {
    const __nv_bfloat16* __restrict__ Bhi = layer ? g_B2hi : g_B1hi;
    const __nv_bfloat16* __restrict__ Blo = layer ? g_B2lo : g_B1lo;
    const __nv_bfloat16* __restrict__ Ahi = g_Ahi;
    const __nv_bfloat16* __restrict__ Alo = g_Alo;

    __shared__ __align__(16) __nv_bfloat16 sAh[2][A_ELEMS];
    __shared__ __align__(16) __nv_bfloat16 sAl[2][A_ELEMS];
    __shared__ __align__(16) __nv_bfloat16 sBh[2][B_ELEMS];
    __shared__ __align__(16) __nv_bfloat16 sBl[2][B_ELEMS];
    __shared__ float s_red[2][128];

    int tid = threadIdx.x, lane = tid & 31, wid = tid >> 5;
    int row0 = blockIdx.y * 128, col0 = blockIdx.x * 64;
    int wm0 = (wid >> 1) * 32, wn0 = (wid & 1) * 32;

    float c[2][4][4] = {};

    int arow = tid >> 1, ahalf = tid & 1;
    int grow = row0 + arow;
    size_t agoff = (size_t)(grow < NN ? grow : 0) * K + ahalf * 8;
    int asoff = arow * ASTRIDE + ahalf * 8;
    int bt = tid & 127;
    int brow = bt >> 3, bchunk = bt & 7;
    int bsoff = brow * BSTRIDE + bchunk * 8;
    size_t bgoff = (size_t)brow * HC + col0 + bchunk * 8;

    uint32_t sAh_b = (uint32_t)__cvta_generic_to_shared(sAh);
    uint32_t sAl_b = (uint32_t)__cvta_generic_to_shared(sAl);
    uint32_t sBh_b = (uint32_t)__cvta_generic_to_shared(sBh);
    uint32_t sBl_b = (uint32_t)__cvta_generic_to_shared(sBl);

    uint32_t aoff0 = ((wm0 + (lane & 15)) * ASTRIDE + (lane >> 4) * 8) * 2;
    uint32_t aoff1 = ((wm0 + 16 + (lane & 15)) * ASTRIDE + (lane >> 4) * 8) * 2;
    uint32_t boff0 = ((lane & 15) * BSTRIDE + wn0 + (lane >> 4) * 8) * 2;
    uint32_t boff1 = ((lane & 15) * BSTRIDE + wn0 + 16 + (lane >> 4) * 8) * 2;

    const int nk = K / 16;

    auto load_stage = [&](int kk, int st) {
        uint32_t ab = st * (A_ELEMS * 2);
        cp16(sAh_b + ab + asoff * 2, Ahi + agoff + kk);
        cp16(sAl_b + ab + asoff * 2, Alo + agoff + kk);
        uint32_t bb = st * (B_ELEMS * 2);
        if (tid < 128) cp16(sBh_b + bb + bsoff * 2, Bhi + (size_t)kk * HC + bgoff);
        else           cp16(sBl_b + bb + bsoff * 2, Blo + (size_t)kk * HC + bgoff);
    };

    load_stage(0, 0);
    cp_commit();

    for (int i = 0; i < nk; i++) {
        if (i + 1 < nk) load_stage((i + 1) * 16, (i + 1) & 1);
        cp_commit();
        cp_wait<1>();
        __syncthreads();

        int st = i & 1;
        uint32_t ab = st * (A_ELEMS * 2);
        uint32_t bb = st * (B_ELEMS * 2);
        uint32_t ah[2][4], al[2][4], bh[4][2], bl[4][2];
        ldsm_x4(sAh_b + ab + aoff0, ah[0][0], ah[0][1], ah[0][2], ah[0][3]);
        ldsm_x4(sAh_b + ab + aoff1, ah[1][0], ah[1][1], ah[1][2], ah[1][3]);
        ldsm_x4(sAl_b + ab + aoff0, al[0][0], al[0][1], al[0][2], al[0][3]);
        ldsm_x4(sAl_b + ab + aoff1, al[1][0], al[1][1], al[1][2], al[1][3]);
        ldsm_x4t(sBh_b + bb + boff0, bh[0][0], bh[0][1], bh[1][0], bh[1][1]);
        ldsm_x4t(sBh_b + bb + boff1, bh[2][0], bh[2][1], bh[3][0], bh[3][1]);
        ldsm_x4t(sBl_b + bb + boff0, bl[0][0], bl[0][1], bl[1][0], bl[1][1]);
        ldsm_x4t(sBl_b + bb + boff1, bl[2][0], bl[2][1], bl[3][0], bl[3][1]);

        #pragma unroll
        for (int mi = 0; mi < 2; mi++)
            #pragma unroll
            for (int ni = 0; ni < 4; ni++) {
                mma_bf16(c[mi][ni], ah[mi], bh[ni]);
                mma_bf16(c[mi][ni], ah[mi], bl[ni]);
                mma_bf16(c[mi][ni], al[mi], bh[ni]);
            }
        __syncthreads();
    }

    // ---- write h tile ----
    int rbase = row0 + wm0 + (lane >> 2);
    int cbase = col0 + wn0 + (lane & 3) * 2;
    #pragma unroll
    for (int mi = 0; mi < 2; mi++)
        #pragma unroll
        for (int ni = 0; ni < 4; ni++) {
            int r = rbase + mi * 16;
            int cc = cbase + ni * 8;
            if (r < NN)
                *(float2*)(g_h + (size_t)r * HC + cc) = make_float2(c[mi][ni][0], c[mi][ni][1]);
            if (r + 8 < NN)
                *(float2*)(g_h + (size_t)(r + 8) * HC + cc) = make_float2(c[mi][ni][2], c[mi][ni][3]);
        }

    // ---- fused a_src/a_dst for this head (head = blockIdx.x) ----
    const float* asp = as_ + blockIdx.x * CC;
    const float* adp = ad_ + blockIdx.x * CC;
    float sacc[4] = {0, 0, 0, 0}, dacc[4] = {0, 0, 0, 0};
    #pragma unroll
    for (int ni = 0; ni < 4; ni++) {
        int c0 = wn0 + (lane & 3) * 2 + ni * 8;
        float a0 = asp[c0], a1 = asp[c0 + 1];
        float d0 = adp[c0], d1 = adp[c0 + 1];
        #pragma unroll
        for (int mi = 0; mi < 2; mi++) {
            sacc[mi * 2 + 0] += c[mi][ni][0] * a0 + c[mi][ni][1] * a1;
            sacc[mi * 2 + 1] += c[mi][ni][2] * a0 + c[mi][ni][3] * a1;
            dacc[mi * 2 + 0] += c[mi][ni][0] * d0 + c[mi][ni][1] * d1;
            dacc[mi * 2 + 1] += c[mi][ni][2] * d0 + c[mi][ni][3] * d1;
        }
    }
    #pragma unroll
    for (int q = 0; q < 4; q++) {
        sacc[q] += __shfl_xor_sync(0xffffffffu, sacc[q], 1);
        sacc[q] += __shfl_xor_sync(0xffffffffu, sacc[q], 2);
        dacc[q] += __shfl_xor_sync(0xffffffffu, dacc[q], 1);
        dacc[q] += __shfl_xor_sync(0xffffffffu, dacc[q], 2);
    }
    if ((wid & 1) == 0 && (lane & 3) == 0) {
        #pragma unroll
        for (int q = 0; q < 4; q++) {
            int rr = wm0 + (lane >> 2) + 8 * (q & 1) + 16 * (q >> 1);
            s_red[0][rr] = sacc[q];
            s_red[1][rr] = dacc[q];
        }
    }
    __syncthreads();
    if ((wid & 1) == 1 && (lane & 3) == 0) {
        #pragma unroll
        for (int q = 0; q < 4; q++) {
            int rr = wm0 + (lane >> 2) + 8 * (q & 1) + 16 * (q >> 1);
            int r = row0 + rr;
            if (r < NN) {
                g_asrc[r * 4 + blockIdx.x] = s_red[0][rr] + sacc[q];
                g_adst[r * 4 + blockIdx.x] = s_red[1][rr] + dacc[q];
            }
        }
    }
}

// ---------------- launch ----------------------------------------------------
extern "C" void kernel_launch(void* const* d_in, const int* in_sizes, int n_in,
                              void* d_out, int out_size) {
    const float* x    = (const float*)d_in[0];
    const float* ef   = (const float*)d_in[1];
    const int*   ei   = (const int*)  d_in[2];
    const float* W1   = (const float*)d_in[3];
    const float* as1  = (const float*)d_in[4];
    const float* ad1  = (const float*)d_in[5];
    const float* ae1  = (const float*)d_in[6];
    const float* b1   = (const float*)d_in[7];
    const float* eW1  = (const float*)d_in[8];
    const float* W2   = (const float*)d_in[9];
    const float* as2  = (const float*)d_in[10];
    const float* ad2  = (const float*)d_in[11];
    const float* ae2  = (const float*)d_in[12];
    const float* b2   = (const float*)d_in[13];
    const float* eW2  = (const float*)d_in[14];
    float* out = (float*)d_out;

    const int* src = ei;
    const int* dst = ei + NE;

    const int EB = (NE + 255) / 256;
    const int NB = (NN + 1023) / 1024;      // 49 == NBCH
    const int PB = 1184;                    // persistent agg blocks
    const dim3 GG(4, (NN + 127) / 128);

    static cudaStream_t s2 = nullptr;
    static cudaEvent_t evFork = nullptr, evM = nullptr, evJoin = nullptr;
    if (s2 == nullptr) {
        cudaStreamCreateWithFlags(&s2, cudaStreamNonBlocking);
        cudaEventCreateWithFlags(&evFork, cudaEventDisableTiming);
        cudaEventCreateWithFlags(&evM, cudaEventDisableTiming);
        cudaEventCreateWithFlags(&evJoin, cudaEventDisableTiming);
    }

    // fork: s2 runs k_M -> k_split -> tgemm(layer1) while main does CSR + elog
    cudaEventRecord(evFork, 0);
    cudaStreamWaitEvent(s2, evFork, 0);

    k_M<<<1, 512, 0, s2>>>(eW1, ae1, eW2, ae2);
    cudaEventRecord(evM, s2);
    k_split<<<(NN * FIN + FIN * HC + HC * HC + 255) / 256, 256, 0, s2>>>(x, W1, W2);
    k_tgemm<<<GG, 256, 0, s2>>>(0, FIN, as1, ad1);
    cudaEventRecord(evJoin, s2);

    // main: CSR chain, then edge logits (needs g_M and g_pos)
    k_deg<<<EB, 256>>>(dst);
    k_bsum<<<NB, 1024>>>();
    k_addoff<<<(NN + 255) / 256, 256>>>();
    k_scatter<<<EB, 256>>>(src, dst);
    cudaStreamWaitEvent(0, evM, 0);
    k_elog<<<NE / 32, 256>>>(ef);

    // join: need g_h / g_asrc / g_adst from tgemm1
    cudaStreamWaitEvent(0, evJoin, 0);

    // layer 1 aggregation (persistent work queue)
    k_agg<1><<<PB, 256>>>(b1, nullptr);

    // layer 2
    k_tgemm<<<GG, 256>>>(1, HC, as2, ad2);
    k_agg<2><<<PB, 256>>>(b2, out);
}